// round 16
// baseline (speedup 1.0000x reference)
#include <cuda_runtime.h>
#include <cuda_fp16.h>
#include <cstdint>
#include <math.h>

#define E_ 8
#define H_ 2048
#define F_ 1024
#define D_ 2048
#define T_ 2048
#define TOPK_ 4
#define R_ 8
#define SCALING_ 2.0f
#define LIMIT_ 7.0f
#define ACT_ALPHA_ 1.702f

// ---- scratch (__device__ globals; allocation-free per harness rules) ----
// g_cnt is zero at module load and re-zeroed at the END of k_combine, so every
// kernel_launch (correctness run and each graph replay) starts with g_cnt == 0.
__device__ float g_w[E_ * T_];
__device__ int   g_cnt[E_];
__device__ int   g_list[E_ * T_];
__device__ int   g_slot[E_ * T_];
__device__ __half g_xh[(size_t)T_ * H_];         // x in fp16
__device__ __half g_w1h[(size_t)E_ * D_ * H_];   // (gate_up + 2*A1@B1)^T [e][d][h]
__device__ __half g_w2h[(size_t)E_ * H_ * F_];   // (down + 2*A2@B2)^T [e][h][f]
__device__ __half g_gw[(size_t)E_ * T_ * F_];    // compacted gatedw fp16
__device__ float g_outc[(size_t)E_ * T_ * H_];   // per-expert contributions fp32

#define CP16(dst_u32, src_ptr) \
    asm volatile("cp.async.cg.shared.global [%0], [%1], 16;" :: "r"(dst_u32), "l"(src_ptr))
#define CP_COMMIT asm volatile("cp.async.commit_group;")
#define CP_WAIT2  asm volatile("cp.async.wait_group 2;")

__device__ __forceinline__ void ldsm4(uint32_t& r0, uint32_t& r1, uint32_t& r2,
                                      uint32_t& r3, uint32_t addr) {
    asm volatile("ldmatrix.sync.aligned.m8n8.x4.shared.b16 {%0,%1,%2,%3}, [%4];"
        : "=r"(r0), "=r"(r1), "=r"(r2), "=r"(r3) : "r"(addr));
}

__device__ __forceinline__ void mma16816(float* acc, uint32_t a0, uint32_t a1,
                                         uint32_t a2, uint32_t a3,
                                         uint32_t b0, uint32_t b1) {
    asm volatile(
        "mma.sync.aligned.m16n8k16.row.col.f32.f16.f16.f32 "
        "{%0,%1,%2,%3}, {%4,%5,%6,%7}, {%8,%9}, {%0,%1,%2,%3};"
        : "+f"(acc[0]), "+f"(acc[1]), "+f"(acc[2]), "+f"(acc[3])
        : "r"(a0), "r"(a1), "r"(a2), "r"(a3), "r"(b0), "r"(b1));
}

// Stage: A 0, B 10240; rows 32 fp16 (64B) + 16B pad = 80B (conflict-free ldmatrix).
// 128 rows * 80B = 10240 per array; stage 20480; 4 stages.
#define ROWB_ 80
#define ASZ_ 10240
#define STG_ 20480
#define NSTG_ 4
#define SMEM_SZ_ (NSTG_ * STG_)
#define MISTR_ (16 * ROWB_)   // 1280

// 1-term fp16 chunk (k32), warp tile 64x32 (8 warps)
__device__ __forceinline__ void compute_chunk1(uint32_t st, float acc[4][4][4],
                                               int a_base, int b_base) {
    uint32_t Ah = st, Bs = st + ASZ_;
#pragma unroll
    for (int ks = 0; ks < 2; ks++) {
        int kb = ks * 32;
        uint32_t B[4][2];
#pragma unroll
        for (int p = 0; p < 2; p++) {
            uint32_t r0, r1, r2, r3;
            ldsm4(r0, r1, r2, r3, Bs + b_base + p * MISTR_ + kb);
            B[2 * p][0] = r0; B[2 * p][1] = r1;
            B[2 * p + 1][0] = r2; B[2 * p + 1][1] = r3;
        }
        uint32_t A[4][4];
#pragma unroll
        for (int mi = 0; mi < 4; mi++)
            ldsm4(A[mi][0], A[mi][1], A[mi][2], A[mi][3],
                  Ah + a_base + mi * MISTR_ + kb);
#pragma unroll
        for (int ni = 0; ni < 4; ni++)
#pragma unroll
            for (int mi = 0; mi < 4; mi++)
                mma16816(acc[mi][ni], A[mi][0], A[mi][1], A[mi][2], A[mi][3],
                         B[ni][0], B[ni][1]);
    }
}

// ===========================================================================
// K_conv (merged): route (blocks 0..7) + X->fp16 + convert/transpose weights
// with the rank-8 LoRA update folded in:  W' = W + 2 * A @ B.
// blocks: [0,8) route, [8,+4096) X, [+16384) w1, [+8192) w2.
// g_cnt enters this kernel already zeroed (module init / end of k_combine).
// ===========================================================================
__global__ void __launch_bounds__(256)
k_conv(const float* __restrict__ X, const float* __restrict__ gup,
       const float* __restrict__ dn,
       const float* __restrict__ A1, const float* __restrict__ B1,
       const float* __restrict__ A2, const float* __restrict__ B2,
       const float* __restrict__ rw, const int* __restrict__ idx) {
    __shared__ __half hs[32][66];
    __shared__ float a_s[64][8];
    __shared__ float b_s[8][32];
    int b = blockIdx.x;
    int tid = threadIdx.x;

    if (b < 8) {                          // ---- routing ----
        int t = b * 256 + tid;
        if (t >= T_) return;
        float acc[E_];
        int act[E_];
#pragma unroll
        for (int j = 0; j < E_; j++) { acc[j] = 0.0f; act[j] = 0; }
        for (int k = 0; k < TOPK_; k++) {
            int e = idx[t * TOPK_ + k];
            float v = rw[t * TOPK_ + k];
#pragma unroll
            for (int j = 0; j < E_; j++)
                if (j == e) { acc[j] += v; act[j] = 1; }
        }
#pragma unroll
        for (int j = 0; j < E_; j++) {
            g_w[j * T_ + t] = acc[j];
            int s = -1;
            if (act[j]) {
                s = atomicAdd(&g_cnt[j], 1);
                g_list[j * T_ + s] = t;
            }
            g_slot[j * T_ + t] = s;
        }
        return;
    }
    if (b < 8 + 4096) {                   // ---- convert X ----
        int i = (b - 8) * 256 + tid;
        float4 v = ((const float4*)X)[i];
        __half2* ph = (__half2*)g_xh;
        ph[i * 2]     = __halves2half2(__float2half_rn(v.x), __float2half_rn(v.y));
        ph[i * 2 + 1] = __halves2half2(__float2half_rn(v.z), __float2half_rn(v.w));
        return;
    }
    const float *src, *la, *lb;
    __half* dst;
    int RR, CC, c0, r0, e;
    if (b < 8 + 4096 + 16384) {           // gup [E][H][D] + 2*A1@B1 -> w1h [E][D][H]
        int i = b - 8 - 4096;
        RR = H_; CC = D_;
        c0 = (i & 63) * 32; r0 = ((i >> 6) & 31) * 64; e = i >> 11;
        src = gup; dst = g_w1h; la = A1; lb = B1;
    } else {                              // dn [E][F][H] + 2*A2@B2 -> w2h [E][H][F]
        int i = b - 8 - 4096 - 16384;
        RR = F_; CC = H_;
        c0 = (i & 63) * 32; r0 = ((i >> 6) & 15) * 64; e = i >> 10;
        src = dn; dst = g_w2h; la = A2; lb = B2;
    }
    int tx = tid & 31, ty = tid >> 5;

    {
        int rl = tid >> 2, pp = (tid & 3) * 2;
        float2 av = *(const float2*)(la + ((size_t)e * RR + r0 + rl) * 8 + pp);
        a_s[rl][pp] = av.x; a_s[rl][pp + 1] = av.y;
        int p = tid >> 5, cc = tid & 31;
        b_s[p][cc] = lb[((size_t)e * 8 + p) * CC + c0 + cc];
    }
    __syncthreads();

    const float* s = src + (size_t)e * RR * CC;
#pragma unroll
    for (int j = 0; j < 8; j++) {
        int rl = ty + j * 8;
        float v = s[(size_t)(r0 + rl) * CC + c0 + tx];
        float lor = 0.0f;
#pragma unroll
        for (int p = 0; p < 8; p++) lor += a_s[rl][p] * b_s[p][tx];
        hs[tx][rl] = __float2half_rn(v + SCALING_ * lor);
    }
    __syncthreads();
    size_t dbase = (size_t)e * RR * CC;
#pragma unroll
    for (int jj = 0; jj < 4; jj++) {
        int cl = ty + jj * 8;
        __half2 hv = __halves2half2(hs[cl][tx * 2], hs[cl][tx * 2 + 1]);
        *(__half2*)(dst + dbase + (size_t)(c0 + cl) * RR + r0 + tx * 2) = hv;
    }
}

// ===========================================================================
// K2 (gathered): HMMA GEMM1 (1-term fp16, LoRA pre-folded), 256 threads,
// CTA tile 128x128, warp 64x32, 4-stage; grid (D/128, 16 max m-tiles, E)
// ===========================================================================
__global__ void __launch_bounds__(256, 2)
k_gemm1(const float* __restrict__ bias) {
    int e = blockIdx.z, m0 = blockIdx.y * 128, n0 = blockIdx.x * 128;
    int cnt = g_cnt[e];
    if (m0 >= cnt) return;
    extern __shared__ char smem[];
    uint32_t sb = (uint32_t)__cvta_generic_to_shared(smem);
    int tid = threadIdx.x;
    int wid = tid >> 5, lane = tid & 31;
    int wr = wid >> 2, wc = wid & 3, g = lane >> 2, q = lane & 3;

    int a_base = (wr * 64 + (lane & 15)) * ROWB_ + (lane >> 4) * 16;
    int grp = lane >> 3, wth = lane & 7;
    int b_base = (wc * 32 + wth + ((grp >= 2) ? 8 : 0)) * ROWB_ + (grp & 1) * 16;

    int row = tid >> 1, seg = tid & 1;
    int tok = g_list[e * T_ + (m0 + row < cnt ? m0 + row : m0)];

    float acc[4][4][4];
#pragma unroll
    for (int a = 0; a < 4; a++)
#pragma unroll
        for (int b = 0; b < 4; b++)
#pragma unroll
            for (int c = 0; c < 4; c++) acc[a][b][c] = 0.0f;

    auto issue = [&](int c, int stage) {
        int k0 = c * 32 + seg * 16;
        uint32_t d = sb + stage * STG_ + row * ROWB_ + seg * 32;
        const __half* sxh = g_xh + (size_t)tok * H_ + k0;
        const __half* swh = g_w1h + ((size_t)e * D_ + n0 + row) * H_ + k0;
        CP16(d,            sxh);  CP16(d + 16,        sxh + 8);
        CP16(d + ASZ_,     swh);  CP16(d + ASZ_ + 16, swh + 8);
    };
    issue(0, 0); CP_COMMIT;
    issue(1, 1); CP_COMMIT;
    issue(2, 2); CP_COMMIT;
    const int NCH = H_ / 32;
    for (int c = 0; c < NCH; c++) {
        CP_WAIT2;
        __syncthreads();
        if (c + 3 < NCH) issue(c + 3, (c + 3) & (NSTG_ - 1));
        CP_COMMIT;
        compute_chunk1(sb + (c & (NSTG_ - 1)) * STG_, acc, a_base, b_base);
    }
    __syncthreads();

    // ---- epilogue: bias + clamp + GLU + w-fold ----
    float* bias_s = (float*)smem;            // [128]
    float* w_s    = (float*)(smem + 512);    // [128]
    if (tid < 128) {
        bias_s[tid] = bias[(size_t)e * D_ + n0 + tid];
        w_s[tid] = (m0 + tid < cnt) ? g_w[e * T_ + g_list[e * T_ + m0 + tid]] : 0.0f;
    }
    __syncthreads();

#pragma unroll
    for (int mi = 0; mi < 4; mi++) {
#pragma unroll
        for (int ni = 0; ni < 4; ni++) {
            int c = wc * 32 + ni * 8 + q * 2;
            float2 bia = *(const float2*)&bias_s[c];
#pragma unroll
            for (int h = 0; h < 2; h++) {
                int rr = wr * 64 + mi * 16 + g + h * 8;
                if (m0 + rr >= cnt) continue;
                float gate = acc[mi][ni][h * 2 + 0] + bia.x;
                float up   = acc[mi][ni][h * 2 + 1] + bia.y;
                gate = fminf(gate, LIMIT_);
                up = fminf(fmaxf(up, -LIMIT_), LIMIT_);
                float glu = gate / (1.0f + expf(-ACT_ALPHA_ * gate));
                float val = w_s[rr] * (up + 1.0f) * glu;
                size_t oidx = ((size_t)e * T_ + m0 + rr) * F_ + ((n0 + c) >> 1);
                g_gw[oidx] = __float2half_rn(val);
            }
        }
    }
}

// ===========================================================================
// K4 (gathered): HMMA GEMM2 (1-term fp16, LoRA pre-folded), 256 threads,
// 4-stage; grid (H/128, 16 max m-tiles, E)
// ===========================================================================
__global__ void __launch_bounds__(256, 2)
k_gemm2(const float* __restrict__ bias2) {
    int e = blockIdx.z, m0 = blockIdx.y * 128, n0 = blockIdx.x * 128;
    int cnt = g_cnt[e];
    if (m0 >= cnt) return;
    extern __shared__ char smem[];
    uint32_t sb = (uint32_t)__cvta_generic_to_shared(smem);
    int tid = threadIdx.x;
    int wid = tid >> 5, lane = tid & 31;
    int wr = wid >> 2, wc = wid & 3, g = lane >> 2, q = lane & 3;

    int a_base = (wr * 64 + (lane & 15)) * ROWB_ + (lane >> 4) * 16;
    int grp = lane >> 3, wth = lane & 7;
    int b_base = (wc * 32 + wth + ((grp >= 2) ? 8 : 0)) * ROWB_ + (grp & 1) * 16;

    int row = tid >> 1, seg = tid & 1;

    float acc[4][4][4];
#pragma unroll
    for (int a = 0; a < 4; a++)
#pragma unroll
        for (int b = 0; b < 4; b++)
#pragma unroll
            for (int c = 0; c < 4; c++) acc[a][b][c] = 0.0f;

    auto issue = [&](int c, int stage) {
        int f0 = c * 32 + seg * 16;
        uint32_t d = sb + stage * STG_ + row * ROWB_ + seg * 32;
        const __half* sah = g_gw  + ((size_t)e * T_ + m0 + row) * F_ + f0;
        const __half* sbh = g_w2h + ((size_t)e * H_ + n0 + row) * F_ + f0;
        CP16(d,            sah);  CP16(d + 16,        sah + 8);
        CP16(d + ASZ_,     sbh);  CP16(d + ASZ_ + 16, sbh + 8);
    };
    issue(0, 0); CP_COMMIT;
    issue(1, 1); CP_COMMIT;
    issue(2, 2); CP_COMMIT;
    const int NCH = F_ / 32;
    for (int c = 0; c < NCH; c++) {
        CP_WAIT2;
        __syncthreads();
        if (c + 3 < NCH) issue(c + 3, (c + 3) & (NSTG_ - 1));
        CP_COMMIT;
        compute_chunk1(sb + (c & (NSTG_ - 1)) * STG_, acc, a_base, b_base);
    }
    __syncthreads();

    // ---- epilogue: + w*bias2; store fp32 outc ----
    float* bb_s = (float*)smem;            // [128]
    float* w_s  = (float*)(smem + 512);    // [128]
    if (tid < 128) {
        bb_s[tid] = bias2[(size_t)e * H_ + n0 + tid];
        w_s[tid] = (m0 + tid < cnt) ? g_w[e * T_ + g_list[e * T_ + m0 + tid]] : 0.0f;
    }
    __syncthreads();

#pragma unroll
    for (int mi = 0; mi < 4; mi++) {
#pragma unroll
        for (int ni = 0; ni < 4; ni++) {
            int c = wc * 32 + ni * 8 + q * 2;
            float2 bb = *(const float2*)&bb_s[c];
#pragma unroll
            for (int h = 0; h < 2; h++) {
                int rr = wr * 64 + mi * 16 + g + h * 8;
                if (m0 + rr >= cnt) continue;
                float wt = w_s[rr];
                float v0 = acc[mi][ni][h * 2 + 0] + wt * bb.x;
                float v1 = acc[mi][ni][h * 2 + 1] + wt * bb.y;
                *(float2*)(g_outc + ((size_t)e * T_ + m0 + rr) * H_ + n0 + c) =
                    make_float2(v0, v1);
            }
        }
    }
}

// ===========================================================================
// K5: combine per-expert contributions -> out; re-zero g_cnt for next replay
// ===========================================================================
__global__ void __launch_bounds__(128)
k_combine(float* __restrict__ out) {
    int t = blockIdx.x;
    int tid = threadIdx.x;
    int slots[E_];
#pragma unroll
    for (int e = 0; e < E_; e++) slots[e] = g_slot[e * T_ + t];
#pragma unroll
    for (int k = 0; k < 4; k++) {
        int h = tid * 4 + k * 512;
        float4 acc = make_float4(0.f, 0.f, 0.f, 0.f);
#pragma unroll
        for (int e = 0; e < E_; e++) {
            int s = slots[e];
            if (s >= 0) {
                float4 v = *(const float4*)(g_outc + ((size_t)e * T_ + s) * H_ + h);
                acc.x += v.x; acc.y += v.y; acc.z += v.z; acc.w += v.w;
            }
        }
        *(float4*)(out + (size_t)t * H_ + h) = acc;
    }
    if (blockIdx.x == 0 && tid < E_) g_cnt[tid] = 0;   // ready for next launch
}

// ===========================================================================
extern "C" void kernel_launch(void* const* d_in, const int* in_sizes, int n_in,
                              void* d_out, int out_size) {
    const float* x      = (const float*)d_in[0];
    const float* rw     = (const float*)d_in[1];
    const float* gup    = (const float*)d_in[2];
    const float* gup_b  = (const float*)d_in[3];
    const float* dn     = (const float*)d_in[4];
    const float* dn_b   = (const float*)d_in[5];
    const float* A1     = (const float*)d_in[6];
    const float* B1     = (const float*)d_in[7];
    const float* A2     = (const float*)d_in[8];
    const float* B2     = (const float*)d_in[9];
    const int*   ri     = (const int*)d_in[10];   // int32 (JAX x64 off)
    float* out = (float*)d_out;

    static bool attr_done = false;
    if (!attr_done) {
        cudaFuncSetAttribute(k_gemm1, cudaFuncAttributeMaxDynamicSharedMemorySize, SMEM_SZ_);
        cudaFuncSetAttribute(k_gemm2, cudaFuncAttributeMaxDynamicSharedMemorySize, SMEM_SZ_);
        attr_done = true;
    }

    k_conv<<<8 + 4096 + 16384 + 8192, 256>>>(x, gup, dn, A1, B1, A2, B2, rw, ri);
    k_gemm1<<<dim3(D_ / 128, T_ / 128, E_), 256, SMEM_SZ_>>>(gup_b);
    k_gemm2<<<dim3(H_ / 128, T_ / 128, E_), 256, SMEM_SZ_>>>(dn_b);
    k_combine<<<T_, 128>>>(out);
}

// round 17
// speedup vs baseline: 1.4044x; 1.4044x over previous
#include <cuda_runtime.h>
#include <cuda_fp16.h>
#include <cstdint>
#include <math.h>

#define E_ 8
#define H_ 2048
#define F_ 1024
#define D_ 2048
#define T_ 2048
#define TOPK_ 4
#define R_ 8
#define SCALING_ 2.0f
#define LIMIT_ 7.0f
#define ACT_ALPHA_ 1.702f

// ---- scratch (__device__ globals; allocation-free per harness rules) ----
__device__ float g_w[E_ * T_];
__device__ int   g_cnt[E_];
__device__ int   g_list[E_ * T_];
__device__ int   g_slot[E_ * T_];
__device__ __half g_xh[(size_t)T_ * H_];         // x in fp16
__device__ __half g_w1h[(size_t)E_ * D_ * H_];   // (gate_up + 2*A1@B1)^T [e][d][h]
__device__ __half g_w2h[(size_t)E_ * H_ * F_];   // (down + 2*A2@B2)^T [e][h][f]
__device__ __half g_gw[(size_t)E_ * T_ * F_];    // compacted gatedw fp16
__device__ float g_outc[(size_t)E_ * T_ * H_];   // per-expert contributions fp32

#define CP16(dst_u32, src_ptr) \
    asm volatile("cp.async.cg.shared.global [%0], [%1], 16;" :: "r"(dst_u32), "l"(src_ptr))
#define CP_COMMIT asm volatile("cp.async.commit_group;")
#define CP_WAIT2  asm volatile("cp.async.wait_group 2;")

__device__ __forceinline__ void ldsm4(uint32_t& r0, uint32_t& r1, uint32_t& r2,
                                      uint32_t& r3, uint32_t addr) {
    asm volatile("ldmatrix.sync.aligned.m8n8.x4.shared.b16 {%0,%1,%2,%3}, [%4];"
        : "=r"(r0), "=r"(r1), "=r"(r2), "=r"(r3) : "r"(addr));
}

__device__ __forceinline__ void mma16816(float* acc, uint32_t a0, uint32_t a1,
                                         uint32_t a2, uint32_t a3,
                                         uint32_t b0, uint32_t b1) {
    asm volatile(
        "mma.sync.aligned.m16n8k16.row.col.f32.f16.f16.f32 "
        "{%0,%1,%2,%3}, {%4,%5,%6,%7}, {%8,%9}, {%0,%1,%2,%3};"
        : "+f"(acc[0]), "+f"(acc[1]), "+f"(acc[2]), "+f"(acc[3])
        : "r"(a0), "r"(a1), "r"(a2), "r"(a3), "r"(b0), "r"(b1));
}

// Stage: A 0, B 10240; rows 32 fp16 (64B) + 16B pad = 80B (conflict-free ldmatrix).
// 128 rows * 80B = 10240 per array; stage 20480; 4 stages.
#define ROWB_ 80
#define ASZ_ 10240
#define STG_ 20480
#define NSTG_ 4
#define SMEM_SZ_ (NSTG_ * STG_)
#define MISTR_ (16 * ROWB_)   // 1280

// 1-term fp16 chunk (k32), warp tile 64x32 (8 warps)
__device__ __forceinline__ void compute_chunk1(uint32_t st, float acc[4][4][4],
                                               int a_base, int b_base) {
    uint32_t Ah = st, Bs = st + ASZ_;
#pragma unroll
    for (int ks = 0; ks < 2; ks++) {
        int kb = ks * 32;
        uint32_t B[4][2];
#pragma unroll
        for (int p = 0; p < 2; p++) {
            uint32_t r0, r1, r2, r3;
            ldsm4(r0, r1, r2, r3, Bs + b_base + p * MISTR_ + kb);
            B[2 * p][0] = r0; B[2 * p][1] = r1;
            B[2 * p + 1][0] = r2; B[2 * p + 1][1] = r3;
        }
        uint32_t A[4][4];
#pragma unroll
        for (int mi = 0; mi < 4; mi++)
            ldsm4(A[mi][0], A[mi][1], A[mi][2], A[mi][3],
                  Ah + a_base + mi * MISTR_ + kb);
#pragma unroll
        for (int ni = 0; ni < 4; ni++)
#pragma unroll
            for (int mi = 0; mi < 4; mi++)
                mma16816(acc[mi][ni], A[mi][0], A[mi][1], A[mi][2], A[mi][3],
                         B[ni][0], B[ni][1]);
    }
}

// ===========================================================================
// K_conv: zero counters + X->fp16 + convert/transpose weights with the
// rank-8 LoRA update folded in:  W' = W + 2 * A @ B.
// ===========================================================================
__global__ void __launch_bounds__(256)
k_conv(const float* __restrict__ X, const float* __restrict__ gup,
       const float* __restrict__ dn,
       const float* __restrict__ A1, const float* __restrict__ B1,
       const float* __restrict__ A2, const float* __restrict__ B2) {
    __shared__ __half hs[32][66];
    __shared__ float a_s[64][8];
    __shared__ float b_s[8][32];
    int b = blockIdx.x;
    int tid = threadIdx.x;
    if (b == 0 && tid < E_) g_cnt[tid] = 0;

    if (b < 4096) {                       // ---- convert X ----
        int i = b * 256 + tid;
        float4 v = ((const float4*)X)[i];
        __half2* ph = (__half2*)g_xh;
        ph[i * 2]     = __halves2half2(__float2half_rn(v.x), __float2half_rn(v.y));
        ph[i * 2 + 1] = __halves2half2(__float2half_rn(v.z), __float2half_rn(v.w));
        return;
    }
    const float *src, *la, *lb;
    __half* dst;
    int RR, CC, c0, r0, e;
    if (b < 4096 + 16384) {               // gup [E][H][D] + 2*A1@B1 -> w1h [E][D][H]
        int i = b - 4096;
        RR = H_; CC = D_;
        c0 = (i & 63) * 32; r0 = ((i >> 6) & 31) * 64; e = i >> 11;
        src = gup; dst = g_w1h; la = A1; lb = B1;
    } else {                              // dn [E][F][H] + 2*A2@B2 -> w2h [E][H][F]
        int i = b - 4096 - 16384;
        RR = F_; CC = H_;
        c0 = (i & 63) * 32; r0 = ((i >> 6) & 15) * 64; e = i >> 10;
        src = dn; dst = g_w2h; la = A2; lb = B2;
    }
    int tx = tid & 31, ty = tid >> 5;

    {
        int rl = tid >> 2, pp = (tid & 3) * 2;
        float2 av = *(const float2*)(la + ((size_t)e * RR + r0 + rl) * 8 + pp);
        a_s[rl][pp] = av.x; a_s[rl][pp + 1] = av.y;
        int p = tid >> 5, cc = tid & 31;
        b_s[p][cc] = lb[((size_t)e * 8 + p) * CC + c0 + cc];
    }
    __syncthreads();

    const float* s = src + (size_t)e * RR * CC;
#pragma unroll
    for (int j = 0; j < 8; j++) {
        int rl = ty + j * 8;
        float v = s[(size_t)(r0 + rl) * CC + c0 + tx];
        float lor = 0.0f;
#pragma unroll
        for (int p = 0; p < 8; p++) lor += a_s[rl][p] * b_s[p][tx];
        hs[tx][rl] = __float2half_rn(v + SCALING_ * lor);
    }
    __syncthreads();
    size_t dbase = (size_t)e * RR * CC;
#pragma unroll
    for (int jj = 0; jj < 4; jj++) {
        int cl = ty + jj * 8;
        __half2 hv = __halves2half2(hs[cl][tx * 2], hs[cl][tx * 2 + 1]);
        *(__half2*)(dst + dbase + (size_t)(c0 + cl) * RR + r0 + tx * 2) = hv;
    }
}

// ===========================================================================
// K0: routing weights + per-expert compacted token lists
// ===========================================================================
__global__ void k_route(const float* __restrict__ rw, const int* __restrict__ idx) {
    int t = blockIdx.x * blockDim.x + threadIdx.x;
    if (t >= T_) return;
    float acc[E_];
    int act[E_];
#pragma unroll
    for (int j = 0; j < E_; j++) { acc[j] = 0.0f; act[j] = 0; }
    for (int k = 0; k < TOPK_; k++) {
        int e = idx[t * TOPK_ + k];
        float v = rw[t * TOPK_ + k];
#pragma unroll
        for (int j = 0; j < E_; j++)
            if (j == e) { acc[j] += v; act[j] = 1; }
    }
#pragma unroll
    for (int j = 0; j < E_; j++) {
        g_w[j * T_ + t] = acc[j];
        int s = -1;
        if (act[j]) {
            s = atomicAdd(&g_cnt[j], 1);
            g_list[j * T_ + s] = t;
        }
        g_slot[j * T_ + t] = s;
    }
}

// ===========================================================================
// K2 (gathered): HMMA GEMM1 (1-term fp16, LoRA pre-folded), 256 threads,
// CTA tile 128x128, warp 64x32, 4-stage; grid (D/128, 16 max m-tiles, E)
// ===========================================================================
__global__ void __launch_bounds__(256, 2)
k_gemm1(const float* __restrict__ bias) {
    int e = blockIdx.z, m0 = blockIdx.y * 128, n0 = blockIdx.x * 128;
    int cnt = g_cnt[e];
    if (m0 >= cnt) return;
    extern __shared__ char smem[];
    uint32_t sb = (uint32_t)__cvta_generic_to_shared(smem);
    int tid = threadIdx.x;
    int wid = tid >> 5, lane = tid & 31;
    int wr = wid >> 2, wc = wid & 3, g = lane >> 2, q = lane & 3;

    int a_base = (wr * 64 + (lane & 15)) * ROWB_ + (lane >> 4) * 16;
    int grp = lane >> 3, wth = lane & 7;
    int b_base = (wc * 32 + wth + ((grp >= 2) ? 8 : 0)) * ROWB_ + (grp & 1) * 16;

    int row = tid >> 1, seg = tid & 1;
    int tok = g_list[e * T_ + (m0 + row < cnt ? m0 + row : m0)];

    float acc[4][4][4];
#pragma unroll
    for (int a = 0; a < 4; a++)
#pragma unroll
        for (int b = 0; b < 4; b++)
#pragma unroll
            for (int c = 0; c < 4; c++) acc[a][b][c] = 0.0f;

    auto issue = [&](int c, int stage) {
        int k0 = c * 32 + seg * 16;
        uint32_t d = sb + stage * STG_ + row * ROWB_ + seg * 32;
        const __half* sxh = g_xh + (size_t)tok * H_ + k0;
        const __half* swh = g_w1h + ((size_t)e * D_ + n0 + row) * H_ + k0;
        CP16(d,            sxh);  CP16(d + 16,        sxh + 8);
        CP16(d + ASZ_,     swh);  CP16(d + ASZ_ + 16, swh + 8);
    };
    issue(0, 0); CP_COMMIT;
    issue(1, 1); CP_COMMIT;
    issue(2, 2); CP_COMMIT;
    const int NCH = H_ / 32;
    for (int c = 0; c < NCH; c++) {
        CP_WAIT2;
        __syncthreads();
        if (c + 3 < NCH) issue(c + 3, (c + 3) & (NSTG_ - 1));
        CP_COMMIT;
        compute_chunk1(sb + (c & (NSTG_ - 1)) * STG_, acc, a_base, b_base);
    }
    __syncthreads();

    // ---- epilogue: bias + clamp + GLU + w-fold ----
    float* bias_s = (float*)smem;            // [128]
    float* w_s    = (float*)(smem + 512);    // [128]
    if (tid < 128) {
        bias_s[tid] = bias[(size_t)e * D_ + n0 + tid];
        w_s[tid] = (m0 + tid < cnt) ? g_w[e * T_ + g_list[e * T_ + m0 + tid]] : 0.0f;
    }
    __syncthreads();

#pragma unroll
    for (int mi = 0; mi < 4; mi++) {
#pragma unroll
        for (int ni = 0; ni < 4; ni++) {
            int c = wc * 32 + ni * 8 + q * 2;
            float2 bia = *(const float2*)&bias_s[c];
#pragma unroll
            for (int h = 0; h < 2; h++) {
                int rr = wr * 64 + mi * 16 + g + h * 8;
                if (m0 + rr >= cnt) continue;
                float gate = acc[mi][ni][h * 2 + 0] + bia.x;
                float up   = acc[mi][ni][h * 2 + 1] + bia.y;
                gate = fminf(gate, LIMIT_);
                up = fminf(fmaxf(up, -LIMIT_), LIMIT_);
                float glu = gate / (1.0f + expf(-ACT_ALPHA_ * gate));
                float val = w_s[rr] * (up + 1.0f) * glu;
                size_t oidx = ((size_t)e * T_ + m0 + rr) * F_ + ((n0 + c) >> 1);
                g_gw[oidx] = __float2half_rn(val);
            }
        }
    }
}

// ===========================================================================
// K4 (gathered): HMMA GEMM2 (1-term fp16, LoRA pre-folded), 256 threads,
// 4-stage; grid (H/128, 16 max m-tiles, E)
// ===========================================================================
__global__ void __launch_bounds__(256, 2)
k_gemm2(const float* __restrict__ bias2) {
    int e = blockIdx.z, m0 = blockIdx.y * 128, n0 = blockIdx.x * 128;
    int cnt = g_cnt[e];
    if (m0 >= cnt) return;
    extern __shared__ char smem[];
    uint32_t sb = (uint32_t)__cvta_generic_to_shared(smem);
    int tid = threadIdx.x;
    int wid = tid >> 5, lane = tid & 31;
    int wr = wid >> 2, wc = wid & 3, g = lane >> 2, q = lane & 3;

    int a_base = (wr * 64 + (lane & 15)) * ROWB_ + (lane >> 4) * 16;
    int grp = lane >> 3, wth = lane & 7;
    int b_base = (wc * 32 + wth + ((grp >= 2) ? 8 : 0)) * ROWB_ + (grp & 1) * 16;

    int row = tid >> 1, seg = tid & 1;

    float acc[4][4][4];
#pragma unroll
    for (int a = 0; a < 4; a++)
#pragma unroll
        for (int b = 0; b < 4; b++)
#pragma unroll
            for (int c = 0; c < 4; c++) acc[a][b][c] = 0.0f;

    auto issue = [&](int c, int stage) {
        int f0 = c * 32 + seg * 16;
        uint32_t d = sb + stage * STG_ + row * ROWB_ + seg * 32;
        const __half* sah = g_gw  + ((size_t)e * T_ + m0 + row) * F_ + f0;
        const __half* sbh = g_w2h + ((size_t)e * H_ + n0 + row) * F_ + f0;
        CP16(d,            sah);  CP16(d + 16,        sah + 8);
        CP16(d + ASZ_,     sbh);  CP16(d + ASZ_ + 16, sbh + 8);
    };
    issue(0, 0); CP_COMMIT;
    issue(1, 1); CP_COMMIT;
    issue(2, 2); CP_COMMIT;
    const int NCH = F_ / 32;
    for (int c = 0; c < NCH; c++) {
        CP_WAIT2;
        __syncthreads();
        if (c + 3 < NCH) issue(c + 3, (c + 3) & (NSTG_ - 1));
        CP_COMMIT;
        compute_chunk1(sb + (c & (NSTG_ - 1)) * STG_, acc, a_base, b_base);
    }
    __syncthreads();

    // ---- epilogue: + w*bias2; store fp32 outc ----
    float* bb_s = (float*)smem;            // [128]
    float* w_s  = (float*)(smem + 512);    // [128]
    if (tid < 128) {
        bb_s[tid] = bias2[(size_t)e * H_ + n0 + tid];
        w_s[tid] = (m0 + tid < cnt) ? g_w[e * T_ + g_list[e * T_ + m0 + tid]] : 0.0f;
    }
    __syncthreads();

#pragma unroll
    for (int mi = 0; mi < 4; mi++) {
#pragma unroll
        for (int ni = 0; ni < 4; ni++) {
            int c = wc * 32 + ni * 8 + q * 2;
            float2 bb = *(const float2*)&bb_s[c];
#pragma unroll
            for (int h = 0; h < 2; h++) {
                int rr = wr * 64 + mi * 16 + g + h * 8;
                if (m0 + rr >= cnt) continue;
                float wt = w_s[rr];
                float v0 = acc[mi][ni][h * 2 + 0] + wt * bb.x;
                float v1 = acc[mi][ni][h * 2 + 1] + wt * bb.y;
                *(float2*)(g_outc + ((size_t)e * T_ + m0 + rr) * H_ + n0 + c) =
                    make_float2(v0, v1);
            }
        }
    }
}

// ===========================================================================
// K5: combine per-expert contributions -> out (256 threads, 8 floats each)
// ===========================================================================
__global__ void __launch_bounds__(256)
k_combine(float* __restrict__ out) {
    int t = blockIdx.x;
    int tid = threadIdx.x;
    int slots[E_];
#pragma unroll
    for (int e = 0; e < E_; e++) slots[e] = g_slot[e * T_ + t];
    int h = tid * 8;
    float acc[8];
#pragma unroll
    for (int j = 0; j < 8; j++) acc[j] = 0.0f;
#pragma unroll
    for (int e = 0; e < E_; e++) {
        int s = slots[e];
        if (s >= 0) {
            const float* p = g_outc + ((size_t)e * T_ + s) * H_ + h;
            float4 v0 = *(const float4*)p;
            float4 v1 = *(const float4*)(p + 4);
            acc[0] += v0.x; acc[1] += v0.y; acc[2] += v0.z; acc[3] += v0.w;
            acc[4] += v1.x; acc[5] += v1.y; acc[6] += v1.z; acc[7] += v1.w;
        }
    }
    float* dst = out + (size_t)t * H_ + h;
    *(float4*)dst       = make_float4(acc[0], acc[1], acc[2], acc[3]);
    *(float4*)(dst + 4) = make_float4(acc[4], acc[5], acc[6], acc[7]);
}

// ===========================================================================
extern "C" void kernel_launch(void* const* d_in, const int* in_sizes, int n_in,
                              void* d_out, int out_size) {
    const float* x      = (const float*)d_in[0];
    const float* rw     = (const float*)d_in[1];
    const float* gup    = (const float*)d_in[2];
    const float* gup_b  = (const float*)d_in[3];
    const float* dn     = (const float*)d_in[4];
    const float* dn_b   = (const float*)d_in[5];
    const float* A1     = (const float*)d_in[6];
    const float* B1     = (const float*)d_in[7];
    const float* A2     = (const float*)d_in[8];
    const float* B2     = (const float*)d_in[9];
    const int*   ri     = (const int*)d_in[10];   // int32 (JAX x64 off)
    float* out = (float*)d_out;

    static bool attr_done = false;
    if (!attr_done) {
        cudaFuncSetAttribute(k_gemm1, cudaFuncAttributeMaxDynamicSharedMemorySize, SMEM_SZ_);
        cudaFuncSetAttribute(k_gemm2, cudaFuncAttributeMaxDynamicSharedMemorySize, SMEM_SZ_);
        attr_done = true;
    }

    k_conv<<<4096 + 16384 + 8192, 256>>>(x, gup, dn, A1, B1, A2, B2);
    k_route<<<(T_ + 127) / 128, 128>>>(rw, ri);
    k_gemm1<<<dim3(D_ / 128, T_ / 128, E_), 256, SMEM_SZ_>>>(gup_b);
    k_gemm2<<<dim3(H_ / 128, T_ / 128, E_), 256, SMEM_SZ_>>>(dn_b);
    k_combine<<<T_, 256>>>(out);
}